// round 11
// baseline (speedup 1.0000x reference)
#include <cuda_runtime.h>

#define N_NODES 100000
#define N_EDGES 1600000
#define N_GRAPHS 512
#define NEG_SLOPE 0.2f
#define ROW 64                         // padded CSR row size (max in-degree)
#define LOG2E 1.4426950408889634f

// ---------------- scratch (static device globals; no allocs allowed) --------
__device__ __align__(16) float  g_h1[N_NODES * 64];   // h1 messages, fp32
__device__ __align__(16) float  g_as1[N_NODES * 8];   // conv1 att src scores (*log2e)
__device__ __align__(16) float  g_ad1[N_NODES * 8];   // conv1 att dst scores (*log2e)
__device__ float2 g_ap2[N_NODES];         // (as2*log2e, p=h2.Wg) per node
__device__ float  g_ad2[N_NODES];         // ad2*log2e
__device__ float  g_M3[64 * 3];           // W2 @ [att_src2^T | att_dst2^T | Wg]
__device__ float  g_c2;                   // bias2 . Wg
__device__ __align__(16) int g_deg[N_NODES];       // in-degree = append cursor
__device__ __align__(16) int g_csr[N_NODES * ROW]; // padded rows: src per edge

// ---------------- init: deg=0, out=bg, prep (M3, c2) ------------------------
__global__ void k_init_prep(float* __restrict__ out, const float* __restrict__ bg,
                            const float* __restrict__ W2,
                            const float* __restrict__ as2v,
                            const float* __restrict__ ad2v,
                            const float* __restrict__ Wg,
                            const float* __restrict__ bias2) {
    if (blockIdx.x == 0) {
        int t = threadIdx.x;
        if (t < 192) {
            int c = t & 63, j = t >> 6;
            const float* v = (j == 0) ? as2v : (j == 1) ? ad2v : Wg;
            float s = 0.f;
            #pragma unroll 4
            for (int o = 0; o < 128; o++) s += W2[c * 128 + o] * v[o];
            g_M3[c * 3 + j] = s;
        } else if (t < 224) {
            int lane = t - 192;
            float s = 0.f;
            for (int o = lane; o < 128; o += 32) s += bias2[o] * Wg[o];
            #pragma unroll
            for (int o = 16; o; o >>= 1) s += __shfl_xor_sync(0xffffffffu, s, o);
            if (lane == 0) g_c2 = s;
        }
        return;
    }
    int t = (blockIdx.x - 1) * blockDim.x + threadIdx.x;
    if (t < N_NODES) g_deg[t] = 0;
    if (t < N_GRAPHS) out[t] = bg[0];
}

// ---------------- CSR build: single atomic-append pass ----------------------
__global__ void k_scatter(const int* __restrict__ ei) {
    int e = (blockIdx.x * blockDim.x + threadIdx.x) * 4;
    if (e >= N_EDGES) return;
    int4 sv = *(const int4*)(ei + e);
    int4 dv = *(const int4*)(ei + N_EDGES + e);
    int p0 = atomicAdd(&g_deg[dv.x], 1);
    int p1 = atomicAdd(&g_deg[dv.y], 1);
    int p2 = atomicAdd(&g_deg[dv.z], 1);
    int p3 = atomicAdd(&g_deg[dv.w], 1);
    g_csr[dv.x * ROW + p0] = sv.x;
    g_csr[dv.y * ROW + p1] = sv.y;
    g_csr[dv.z * ROW + p2] = sv.z;
    g_csr[dv.w * ROW + p3] = sv.w;
}

// ---------------- GEMM1 + att1 fused: h1 = x @ W1, scores pre-scaled --------
__global__ __launch_bounds__(256) void k_gemm1(const float* __restrict__ x,
                                               const float* __restrict__ W,
                                               const float* __restrict__ att_src,
                                               const float* __restrict__ att_dst) {
    __shared__ float As[75 * 64];   // As[k][r] (A transposed)
    __shared__ float Bs[75 * 64];   // Bs[k][c]
    const int t = threadIdx.x;
    const int m0 = blockIdx.x * 64;
    for (int i = t; i < 75 * 64; i += 256) Bs[i] = W[i];
    for (int i = t; i < 64 * 75; i += 256) {
        int r = i / 75, k = i - r * 75;
        int gi = m0 + r;
        As[k * 64 + r] = (gi < N_NODES) ? x[gi * 75 + k] : 0.f;
    }
    __syncthreads();
    const int tx = t & 15, ty = t >> 4;
    const int r0 = ty * 4, c0 = tx * 4;
    float acc[4][4] = {};
    #pragma unroll 3
    for (int k = 0; k < 75; k++) {
        float4 av = *(const float4*)(As + k * 64 + r0);
        float4 bv = *(const float4*)(Bs + k * 64 + c0);
        float ar[4] = {av.x, av.y, av.z, av.w};
        float br[4] = {bv.x, bv.y, bv.z, bv.w};
        #pragma unroll
        for (int r = 0; r < 4; r++)
            #pragma unroll
            for (int c = 0; c < 4; c++) acc[r][c] += ar[r] * br[c];
    }
    // att1 epilogue: head h = tx>>1; thread pair (tx, tx^1) spans its 8 chans
    const int h = tx >> 1, half = tx & 1;
    float4 sv = *(const float4*)(att_src + h * 8 + half * 4);
    float4 dv = *(const float4*)(att_dst + h * 8 + half * 4);
    #pragma unroll
    for (int r = 0; r < 4; r++) {
        int gi = m0 + r0 + r;
        float ps = acc[r][0]*sv.x + acc[r][1]*sv.y + acc[r][2]*sv.z + acc[r][3]*sv.w;
        float pd = acc[r][0]*dv.x + acc[r][1]*dv.y + acc[r][2]*dv.z + acc[r][3]*dv.w;
        ps += __shfl_xor_sync(0xffffffffu, ps, 1);
        pd += __shfl_xor_sync(0xffffffffu, pd, 1);
        if (gi < N_NODES) {
            *(float4*)(g_h1 + gi * 64 + c0) =
                make_float4(acc[r][0], acc[r][1], acc[r][2], acc[r][3]);
            if (half == 0) {
                g_as1[gi * 8 + h] = ps * LOG2E;   // pre-scale for exp2
                g_ad1[gi * 8 + h] = pd * LOG2E;
            }
        }
    }
}

// ---------------- conv1 aggregation + conv2-score projection, fused ---------
// 8-lane group per node: lane l == head l, owns its 8 channels via 2 float4
// (fp32, no unpack ALU). Self-loop seeded from registers, not CSR.
__global__ void k_edge1(const float* __restrict__ bias1) {
    int w = (blockIdx.x * blockDim.x + threadIdx.x) >> 3;   // node id
    if (w >= N_NODES) return;
    int l = threadIdx.x & 7;                                 // head id
    float adst = g_ad1[w * 8 + l];
    // self-loop contribution (s == w), no csr involved
    float eaS = g_as1[w * 8 + l] + adst;
    eaS = (eaS > 0.f) ? eaS : NEG_SLOPE * eaS;
    float eeS = exp2f(eaS);
    float4 hS0 = *(const float4*)(g_h1 + w * 64 + l * 8);
    float4 hS1 = *(const float4*)(g_h1 + w * 64 + l * 8 + 4);
    float c0a = eeS * hS0.x, c1a = eeS * hS0.y, c2a = eeS * hS0.z, c3a = eeS * hS0.w;
    float c4a = eeS * hS1.x, c5a = eeS * hS1.y, c6a = eeS * hS1.z, c7a = eeS * hS1.w;
    float den = eeS;
    int e0 = w * ROW, e1 = e0 + g_deg[w];
    int e = e0;
    for (; e + 2 <= e1; e += 2) {
        int sA = g_csr[e], sB = g_csr[e + 1];
        float aA = g_as1[sA * 8 + l];
        float aB = g_as1[sB * 8 + l];
        const float* pA = g_h1 + sA * 64 + l * 8;
        const float* pB = g_h1 + sB * 64 + l * 8;
        float4 hA0 = *(const float4*)pA;
        float4 hA1 = *(const float4*)(pA + 4);
        float4 hB0 = *(const float4*)pB;
        float4 hB1 = *(const float4*)(pB + 4);
        float eaA = aA + adst, eaB = aB + adst;
        eaA = (eaA > 0.f) ? eaA : NEG_SLOPE * eaA;
        eaB = (eaB > 0.f) ? eaB : NEG_SLOPE * eaB;
        float eeA = exp2f(eaA), eeB = exp2f(eaB);
        c0a += eeA * hA0.x; c1a += eeA * hA0.y; c2a += eeA * hA0.z; c3a += eeA * hA0.w;
        c4a += eeA * hA1.x; c5a += eeA * hA1.y; c6a += eeA * hA1.z; c7a += eeA * hA1.w;
        c0a += eeB * hB0.x; c1a += eeB * hB0.y; c2a += eeB * hB0.z; c3a += eeB * hB0.w;
        c4a += eeB * hB1.x; c5a += eeB * hB1.y; c6a += eeB * hB1.z; c7a += eeB * hB1.w;
        den += eeA + eeB;
    }
    if (e < e1) {
        int s = g_csr[e];
        float a = g_as1[s * 8 + l];
        const float* p = g_h1 + s * 64 + l * 8;
        float4 h0 = *(const float4*)p;
        float4 h1 = *(const float4*)(p + 4);
        float ea = a + adst;
        ea = (ea > 0.f) ? ea : NEG_SLOPE * ea;
        float ee = exp2f(ea);
        c0a += ee * h0.x; c1a += ee * h0.y; c2a += ee * h0.z; c3a += ee * h0.w;
        c4a += ee * h1.x; c5a += ee * h1.y; c6a += ee * h1.z; c7a += ee * h1.w;
        den += ee;
    }
    float inv = 1.f / den;
    int co = l * 8;
    float4 b0 = *(const float4*)(bias1 + co);
    float4 b1 = *(const float4*)(bias1 + co + 4);
    float v[8];
    v[0] = c0a * inv + b0.x; v[1] = c1a * inv + b0.y;
    v[2] = c2a * inv + b0.z; v[3] = c3a * inv + b0.w;
    v[4] = c4a * inv + b1.x; v[5] = c5a * inv + b1.y;
    v[6] = c6a * inv + b1.z; v[7] = c7a * inv + b1.w;
    #pragma unroll
    for (int j = 0; j < 8; j++)
        v[j] = (v[j] > 0.f) ? v[j] : (__expf(v[j]) - 1.f);   // ELU
    // project x2 row chunk onto the 3 fused conv2 vectors
    float s0 = 0.f, s1 = 0.f, s2 = 0.f;
    #pragma unroll
    for (int j = 0; j < 8; j++) {
        s0 += v[j] * g_M3[(co + j) * 3 + 0];
        s1 += v[j] * g_M3[(co + j) * 3 + 1];
        s2 += v[j] * g_M3[(co + j) * 3 + 2];
    }
    #pragma unroll
    for (int o = 4; o; o >>= 1) {    // group-local reduce (offsets < 8)
        s0 += __shfl_xor_sync(0xffffffffu, s0, o);
        s1 += __shfl_xor_sync(0xffffffffu, s1, o);
        s2 += __shfl_xor_sync(0xffffffffu, s2, o);
    }
    if (l == 0) {
        g_ap2[w] = make_float2(s0 * LOG2E, s2);   // (as2*log2e, p)
        g_ad2[w] = s1 * LOG2E;
    }
}

// ---------------- conv2 aggregation + pool + final linear, scalarized -------
// 8-lane group per node; lane 0 seeds the self contribution from registers.
__global__ void k_edge2(const int* __restrict__ batch,
                        float* __restrict__ out) {
    int w = (blockIdx.x * blockDim.x + threadIdx.x) >> 3;
    if (w >= N_NODES) return;
    int l = threadIdx.x & 7;
    float adst = g_ad2[w];
    float num = 0.f, den = 0.f;
    float2 apW = g_ap2[w];
    if (l == 0) {            // self-loop
        float ea = apW.x + adst;
        ea = (ea > 0.f) ? ea : NEG_SLOPE * ea;
        float ee = exp2f(ea);
        num = ee * apW.y;
        den = ee;
    }
    int e0 = w * ROW, e1 = e0 + g_deg[w];
    int e = e0 + l;
    for (; e + 8 < e1; e += 16) {
        int sA = g_csr[e], sB = g_csr[e + 8];
        float2 apA = g_ap2[sA];
        float2 apB = g_ap2[sB];
        float eaA = apA.x + adst;
        float eaB = apB.x + adst;
        eaA = (eaA > 0.f) ? eaA : NEG_SLOPE * eaA;
        eaB = (eaB > 0.f) ? eaB : NEG_SLOPE * eaB;
        float eeA = exp2f(eaA), eeB = exp2f(eaB);
        num += eeA * apA.y + eeB * apB.y;
        den += eeA + eeB;
    }
    if (e < e1) {
        int s = g_csr[e];
        float2 ap = g_ap2[s];
        float ea = ap.x + adst;
        ea = (ea > 0.f) ? ea : NEG_SLOPE * ea;
        float ee = exp2f(ea);
        num += ee * ap.y;
        den += ee;
    }
    #pragma unroll
    for (int o = 4; o; o >>= 1) {    // group-local reduce (offsets < 8)
        num += __shfl_xor_sync(0xffffffffu, num, o);
        den += __shfl_xor_sync(0xffffffffu, den, o);
    }
    if (l == 0) atomicAdd(out + batch[w], num / den + g_c2);
}

// ---------------- launch: fork gemm1 parallel to CSR build ------------------
extern "C" void kernel_launch(void* const* d_in, const int* in_sizes, int n_in,
                              void* d_out, int out_size) {
    const float* x        = (const float*)d_in[0];
    const int*   ei       = (const int*)  d_in[1];
    const int*   batch    = (const int*)  d_in[2];
    const float* W1       = (const float*)d_in[3];
    const float* att_src1 = (const float*)d_in[4];
    const float* att_dst1 = (const float*)d_in[5];
    const float* bias1    = (const float*)d_in[6];
    const float* W2       = (const float*)d_in[7];
    const float* att_src2 = (const float*)d_in[8];
    const float* att_dst2 = (const float*)d_in[9];
    const float* bias2    = (const float*)d_in[10];
    const float* Wg       = (const float*)d_in[11];
    const float* bg       = (const float*)d_in[12];
    float* out = (float*)d_out;

    static cudaStream_t s2 = 0;
    static cudaEvent_t ev_fork = 0, ev_join = 0;
    if (!s2) {
        cudaStreamCreateWithFlags(&s2, cudaStreamNonBlocking);
        cudaEventCreateWithFlags(&ev_fork, cudaEventDisableTiming);
        cudaEventCreateWithFlags(&ev_join, cudaEventDisableTiming);
    }

    // fork: gemm1 on s2, CSR build on the launch stream
    cudaEventRecord(ev_fork, 0);
    cudaStreamWaitEvent(s2, ev_fork, 0);
    k_gemm1<<<(N_NODES + 63) / 64, 256, 0, s2>>>(x, W1, att_src1, att_dst1);
    cudaEventRecord(ev_join, s2);

    k_init_prep<<<1 + (N_NODES + 255) / 256, 256>>>(out, bg, W2, att_src2,
                                                    att_dst2, Wg, bias2);
    k_scatter<<<(N_EDGES / 4 + 255) / 256, 256>>>(ei);

    cudaStreamWaitEvent(0, ev_join, 0);
    k_edge1<<<(N_NODES * 8 + 255) / 256, 256>>>(bias1);
    k_edge2<<<(N_NODES * 8 + 255) / 256, 256>>>(batch, out);
}

// round 12
// speedup vs baseline: 1.0740x; 1.0740x over previous
#include <cuda_runtime.h>
#include <cuda_bf16.h>

#define N_NODES 100000
#define N_EDGES 1600000
#define N_GRAPHS 512
#define NEG_SLOPE 0.2f
#define ROW 64                         // padded CSR row size (max in-degree)
#define LOG2E 1.4426950408889634f

// ---------------- packed f32x2 helpers (sm_103a) ----------------------------
__device__ __forceinline__ unsigned long long pk2(float lo, float hi) {
    unsigned long long r;
    asm("mov.b64 %0, {%1, %2};" : "=l"(r) : "f"(lo), "f"(hi));
    return r;
}
__device__ __forceinline__ unsigned long long ffma2(unsigned long long a,
                                                    unsigned long long b,
                                                    unsigned long long c) {
    unsigned long long d;
    asm("fma.rn.f32x2 %0, %1, %2, %3;" : "=l"(d) : "l"(a), "l"(b), "l"(c));
    return d;
}
__device__ __forceinline__ float2 upk2(unsigned long long v) {
    float lo, hi;
    asm("mov.b64 {%0, %1}, %2;" : "=f"(lo), "=f"(hi) : "l"(v));
    return make_float2(lo, hi);
}

// ---------------- scratch (static device globals; no allocs allowed) --------
__device__ __align__(16) __nv_bfloat162 g_h1b[N_NODES * 32]; // h1 messages, bf16
__device__ __align__(16) float  g_as1[N_NODES * 8];   // conv1 att src scores (*log2e)
__device__ __align__(16) float  g_ad1[N_NODES * 8];   // conv1 att dst scores (*log2e)
__device__ float2 g_ap2[N_NODES];         // (as2*log2e, p=h2.Wg) per node
__device__ float  g_ad2[N_NODES];         // ad2*log2e
__device__ float  g_M3[64 * 3];           // W2 @ [att_src2^T | att_dst2^T | Wg]
__device__ float  g_c2;                   // bias2 . Wg
__device__ __align__(16) int g_deg[N_NODES];       // in-degree = append cursor
__device__ __align__(16) int g_csr[N_NODES * ROW]; // padded rows: src per edge

// ---------------- init: deg=0, out=bg, prep (M3, c2) ------------------------
__global__ void k_init_prep(float* __restrict__ out, const float* __restrict__ bg,
                            const float* __restrict__ W2,
                            const float* __restrict__ as2v,
                            const float* __restrict__ ad2v,
                            const float* __restrict__ Wg,
                            const float* __restrict__ bias2) {
    if (blockIdx.x == 0) {
        int t = threadIdx.x;
        if (t < 192) {
            int c = t & 63, j = t >> 6;
            const float* v = (j == 0) ? as2v : (j == 1) ? ad2v : Wg;
            float s = 0.f;
            #pragma unroll 4
            for (int o = 0; o < 128; o++) s += W2[c * 128 + o] * v[o];
            g_M3[c * 3 + j] = s;
        } else if (t < 224) {
            int lane = t - 192;
            float s = 0.f;
            for (int o = lane; o < 128; o += 32) s += bias2[o] * Wg[o];
            #pragma unroll
            for (int o = 16; o; o >>= 1) s += __shfl_xor_sync(0xffffffffu, s, o);
            if (lane == 0) g_c2 = s;
        }
        return;
    }
    int t = (blockIdx.x - 1) * blockDim.x + threadIdx.x;
    if (t < N_NODES) g_deg[t] = 0;
    if (t < N_GRAPHS) out[t] = bg[0];
}

// ---------------- CSR build: single atomic-append pass ----------------------
__global__ void k_scatter(const int* __restrict__ ei) {
    int e = (blockIdx.x * blockDim.x + threadIdx.x) * 4;
    if (e >= N_EDGES) return;
    int4 sv = *(const int4*)(ei + e);
    int4 dv = *(const int4*)(ei + N_EDGES + e);
    int p0 = atomicAdd(&g_deg[dv.x], 1);
    int p1 = atomicAdd(&g_deg[dv.y], 1);
    int p2 = atomicAdd(&g_deg[dv.z], 1);
    int p3 = atomicAdd(&g_deg[dv.w], 1);
    g_csr[dv.x * ROW + p0] = sv.x;
    g_csr[dv.y * ROW + p1] = sv.y;
    g_csr[dv.z * ROW + p2] = sv.z;
    g_csr[dv.w * ROW + p3] = sv.w;
}

// ---------------- GEMM1 + att1 fused: h1 = x @ W1, scores pre-scaled --------
__global__ __launch_bounds__(256) void k_gemm1(const float* __restrict__ x,
                                               const float* __restrict__ W,
                                               const float* __restrict__ att_src,
                                               const float* __restrict__ att_dst) {
    __shared__ float As[75 * 64];   // As[k][r] (A transposed)
    __shared__ float Bs[75 * 64];   // Bs[k][c]
    const int t = threadIdx.x;
    const int m0 = blockIdx.x * 64;
    for (int i = t; i < 75 * 64; i += 256) Bs[i] = W[i];
    for (int i = t; i < 64 * 75; i += 256) {
        int r = i / 75, k = i - r * 75;
        int gi = m0 + r;
        As[k * 64 + r] = (gi < N_NODES) ? x[gi * 75 + k] : 0.f;
    }
    __syncthreads();
    const int tx = t & 15, ty = t >> 4;
    const int r0 = ty * 4, c0 = tx * 4;
    float acc[4][4] = {};
    #pragma unroll 3
    for (int k = 0; k < 75; k++) {
        float4 av = *(const float4*)(As + k * 64 + r0);
        float4 bv = *(const float4*)(Bs + k * 64 + c0);
        float ar[4] = {av.x, av.y, av.z, av.w};
        float br[4] = {bv.x, bv.y, bv.z, bv.w};
        #pragma unroll
        for (int r = 0; r < 4; r++)
            #pragma unroll
            for (int c = 0; c < 4; c++) acc[r][c] += ar[r] * br[c];
    }
    // att1 epilogue: head h = tx>>1; thread pair (tx, tx^1) spans its 8 chans
    const int h = tx >> 1, half = tx & 1;
    float4 sv = *(const float4*)(att_src + h * 8 + half * 4);
    float4 dv = *(const float4*)(att_dst + h * 8 + half * 4);
    #pragma unroll
    for (int r = 0; r < 4; r++) {
        int gi = m0 + r0 + r;
        float ps = acc[r][0]*sv.x + acc[r][1]*sv.y + acc[r][2]*sv.z + acc[r][3]*sv.w;
        float pd = acc[r][0]*dv.x + acc[r][1]*dv.y + acc[r][2]*dv.z + acc[r][3]*dv.w;
        ps += __shfl_xor_sync(0xffffffffu, ps, 1);
        pd += __shfl_xor_sync(0xffffffffu, pd, 1);
        if (gi < N_NODES) {
            __nv_bfloat162 b0 = __floats2bfloat162_rn(acc[r][0], acc[r][1]);
            __nv_bfloat162 b1 = __floats2bfloat162_rn(acc[r][2], acc[r][3]);
            uint2 packed = make_uint2(*(unsigned*)&b0, *(unsigned*)&b1);
            *(uint2*)(g_h1b + gi * 32 + tx * 2) = packed;
            if (half == 0) {
                g_as1[gi * 8 + h] = ps * LOG2E;   // pre-scale for exp2
                g_ad1[gi * 8 + h] = pd * LOG2E;
            }
        }
    }
}

// ---------------- conv1 aggregation + conv2-score projection, fused ---------
// 8-lane group per node: lane l == head l, one uint4 (bf16x8) per edge.
// Self-loop from registers; csr batched via int4; f32x2 FMA accumulators.
__global__ void k_edge1(const float* __restrict__ bias1) {
    int w = (blockIdx.x * blockDim.x + threadIdx.x) >> 3;   // node id
    if (w >= N_NODES) return;
    int l = threadIdx.x & 7;                                 // head id
    float adst = g_ad1[w * 8 + l];
    // self-loop contribution (s == w), no csr involved
    float eaS = g_as1[w * 8 + l] + adst;
    eaS = fmaxf(eaS, NEG_SLOPE * eaS);
    float eeS = exp2f(eaS);
    unsigned long long ee2S = pk2(eeS, eeS);
    uint4 rS = *(const uint4*)(g_h1b + w * 32 + l * 4);
    unsigned long long acc0, acc1, acc2, acc3;
    {
        float2 p0 = __bfloat1622float2(*(__nv_bfloat162*)&rS.x);
        float2 p1 = __bfloat1622float2(*(__nv_bfloat162*)&rS.y);
        float2 p2 = __bfloat1622float2(*(__nv_bfloat162*)&rS.z);
        float2 p3 = __bfloat1622float2(*(__nv_bfloat162*)&rS.w);
        unsigned long long z = pk2(0.f, 0.f);
        acc0 = ffma2(pk2(p0.x, p0.y), ee2S, z);
        acc1 = ffma2(pk2(p1.x, p1.y), ee2S, z);
        acc2 = ffma2(pk2(p2.x, p2.y), ee2S, z);
        acc3 = ffma2(pk2(p3.x, p3.y), ee2S, z);
    }
    float den = eeS;
    int e0 = w * ROW, nE = g_deg[w];
    int e = 0;
    #define EDGE1_BODY(sid, aval, rval)                                     \
        {                                                                   \
            float ea_ = (aval) + adst;                                      \
            ea_ = fmaxf(ea_, NEG_SLOPE * ea_);                              \
            float ee_ = exp2f(ea_);                                         \
            unsigned long long ee2_ = pk2(ee_, ee_);                        \
            float2 q0 = __bfloat1622float2(*(__nv_bfloat162*)&(rval).x);    \
            float2 q1 = __bfloat1622float2(*(__nv_bfloat162*)&(rval).y);    \
            float2 q2 = __bfloat1622float2(*(__nv_bfloat162*)&(rval).z);    \
            float2 q3 = __bfloat1622float2(*(__nv_bfloat162*)&(rval).w);    \
            acc0 = ffma2(pk2(q0.x, q0.y), ee2_, acc0);                      \
            acc1 = ffma2(pk2(q1.x, q1.y), ee2_, acc1);                      \
            acc2 = ffma2(pk2(q2.x, q2.y), ee2_, acc2);                      \
            acc3 = ffma2(pk2(q3.x, q3.y), ee2_, acc3);                      \
            den += ee_;                                                     \
        }
    for (; e + 4 <= nE; e += 4) {
        int4 ss = *(const int4*)(g_csr + e0 + e);
        float aA = g_as1[ss.x * 8 + l];
        float aB = g_as1[ss.y * 8 + l];
        float aC = g_as1[ss.z * 8 + l];
        float aD = g_as1[ss.w * 8 + l];
        uint4 rA = *(const uint4*)(g_h1b + ss.x * 32 + l * 4);
        uint4 rB = *(const uint4*)(g_h1b + ss.y * 32 + l * 4);
        uint4 rC = *(const uint4*)(g_h1b + ss.z * 32 + l * 4);
        uint4 rD = *(const uint4*)(g_h1b + ss.w * 32 + l * 4);
        EDGE1_BODY(ss.x, aA, rA)
        EDGE1_BODY(ss.y, aB, rB)
        EDGE1_BODY(ss.z, aC, rC)
        EDGE1_BODY(ss.w, aD, rD)
    }
    for (; e < nE; e++) {
        int s = g_csr[e0 + e];
        float a = g_as1[s * 8 + l];
        uint4 r = *(const uint4*)(g_h1b + s * 32 + l * 4);
        EDGE1_BODY(s, a, r)
    }
    #undef EDGE1_BODY
    float inv = 1.f / den;
    int co = l * 8;
    float4 b0 = *(const float4*)(bias1 + co);
    float4 b1 = *(const float4*)(bias1 + co + 4);
    float2 u0 = upk2(acc0), u1 = upk2(acc1), u2 = upk2(acc2), u3 = upk2(acc3);
    float v[8];
    v[0] = u0.x * inv + b0.x; v[1] = u0.y * inv + b0.y;
    v[2] = u1.x * inv + b0.z; v[3] = u1.y * inv + b0.w;
    v[4] = u2.x * inv + b1.x; v[5] = u2.y * inv + b1.y;
    v[6] = u3.x * inv + b1.z; v[7] = u3.y * inv + b1.w;
    #pragma unroll
    for (int j = 0; j < 8; j++)
        v[j] = (v[j] > 0.f) ? v[j] : (__expf(v[j]) - 1.f);   // ELU
    // project x2 row chunk onto the 3 fused conv2 vectors
    float s0 = 0.f, s1 = 0.f, s2 = 0.f;
    #pragma unroll
    for (int j = 0; j < 8; j++) {
        s0 += v[j] * g_M3[(co + j) * 3 + 0];
        s1 += v[j] * g_M3[(co + j) * 3 + 1];
        s2 += v[j] * g_M3[(co + j) * 3 + 2];
    }
    #pragma unroll
    for (int o = 4; o; o >>= 1) {    // group-local reduce (offsets < 8)
        s0 += __shfl_xor_sync(0xffffffffu, s0, o);
        s1 += __shfl_xor_sync(0xffffffffu, s1, o);
        s2 += __shfl_xor_sync(0xffffffffu, s2, o);
    }
    if (l == 0) {
        g_ap2[w] = make_float2(s0 * LOG2E, s2);   // (as2*log2e, p)
        g_ad2[w] = s1 * LOG2E;
    }
}

// ---------------- conv2 aggregation + pool + final linear, scalarized -------
// 8-lane group per node; lane 0 seeds the self contribution from registers.
__global__ void k_edge2(const int* __restrict__ batch,
                        float* __restrict__ out) {
    int w = (blockIdx.x * blockDim.x + threadIdx.x) >> 3;
    if (w >= N_NODES) return;
    int l = threadIdx.x & 7;
    float adst = g_ad2[w];
    float num = 0.f, den = 0.f;
    float2 apW = g_ap2[w];
    if (l == 0) {            // self-loop
        float ea = apW.x + adst;
        ea = fmaxf(ea, NEG_SLOPE * ea);
        float ee = exp2f(ea);
        num = ee * apW.y;
        den = ee;
    }
    int e0 = w * ROW, e1 = e0 + g_deg[w];
    int e = e0 + l;
    for (; e + 8 < e1; e += 16) {
        int sA = g_csr[e], sB = g_csr[e + 8];
        float2 apA = g_ap2[sA];
        float2 apB = g_ap2[sB];
        float eaA = apA.x + adst;
        float eaB = apB.x + adst;
        eaA = fmaxf(eaA, NEG_SLOPE * eaA);
        eaB = fmaxf(eaB, NEG_SLOPE * eaB);
        float eeA = exp2f(eaA), eeB = exp2f(eaB);
        num += eeA * apA.y + eeB * apB.y;
        den += eeA + eeB;
    }
    if (e < e1) {
        int s = g_csr[e];
        float2 ap = g_ap2[s];
        float ea = ap.x + adst;
        ea = fmaxf(ea, NEG_SLOPE * ea);
        float ee = exp2f(ea);
        num += ee * ap.y;
        den += ee;
    }
    #pragma unroll
    for (int o = 4; o; o >>= 1) {    // group-local reduce (offsets < 8)
        num += __shfl_xor_sync(0xffffffffu, num, o);
        den += __shfl_xor_sync(0xffffffffu, den, o);
    }
    if (l == 0) atomicAdd(out + batch[w], num / den + g_c2);
}

// ---------------- launch: fork gemm1 parallel to CSR build ------------------
extern "C" void kernel_launch(void* const* d_in, const int* in_sizes, int n_in,
                              void* d_out, int out_size) {
    const float* x        = (const float*)d_in[0];
    const int*   ei       = (const int*)  d_in[1];
    const int*   batch    = (const int*)  d_in[2];
    const float* W1       = (const float*)d_in[3];
    const float* att_src1 = (const float*)d_in[4];
    const float* att_dst1 = (const float*)d_in[5];
    const float* bias1    = (const float*)d_in[6];
    const float* W2       = (const float*)d_in[7];
    const float* att_src2 = (const float*)d_in[8];
    const float* att_dst2 = (const float*)d_in[9];
    const float* bias2    = (const float*)d_in[10];
    const float* Wg       = (const float*)d_in[11];
    const float* bg       = (const float*)d_in[12];
    float* out = (float*)d_out;

    static cudaStream_t s2 = 0;
    static cudaEvent_t ev_fork = 0, ev_join = 0;
    if (!s2) {
        cudaStreamCreateWithFlags(&s2, cudaStreamNonBlocking);
        cudaEventCreateWithFlags(&ev_fork, cudaEventDisableTiming);
        cudaEventCreateWithFlags(&ev_join, cudaEventDisableTiming);
    }

    // fork: gemm1 on s2, CSR build on the launch stream
    cudaEventRecord(ev_fork, 0);
    cudaStreamWaitEvent(s2, ev_fork, 0);
    k_gemm1<<<(N_NODES + 63) / 64, 256, 0, s2>>>(x, W1, att_src1, att_dst1);
    cudaEventRecord(ev_join, s2);

    k_init_prep<<<1 + (N_NODES + 255) / 256, 256>>>(out, bg, W2, att_src2,
                                                    att_dst2, Wg, bias2);
    k_scatter<<<(N_EDGES / 4 + 255) / 256, 256>>>(ei);

    cudaStreamWaitEvent(0, ev_join, 0);
    k_edge1<<<(N_NODES * 8 + 255) / 256, 256>>>(bias1);
    k_edge2<<<(N_NODES * 8 + 255) / 256, 256>>>(batch, out);
}

// round 13
// speedup vs baseline: 1.1003x; 1.0245x over previous
#include <cuda_runtime.h>
#include <cuda_bf16.h>

#define N_NODES 100000
#define N_EDGES 1600000
#define N_GRAPHS 512
#define NEG_SLOPE 0.2f
#define ROW 64                         // padded CSR row size (max in-degree)
#define LOG2E 1.4426950408889634f
#define GEMM_BLOCKS ((N_NODES + 63) / 64)   // 1563

// ---------------- scratch (static device globals; no allocs allowed) --------
// NOTE: g_deg and g_out are zero at module load and are RE-ZEROED by the
// kernels that consume them (edge2 / final), so no init pass is needed and
// every kernel_launch call is state-neutral.
__device__ __align__(16) __nv_bfloat162 g_h1b[N_NODES * 32]; // h1 messages, bf16
__device__ __align__(16) float  g_as1[N_NODES * 8];   // conv1 att src scores (*log2e)
__device__ __align__(16) float  g_ad1[N_NODES * 8];   // conv1 att dst scores (*log2e)
__device__ float2 g_ap2[N_NODES];         // (as2*log2e, p=h2.Wg) per node
__device__ float  g_ad2[N_NODES];         // ad2*log2e
__device__ float  g_M3[64 * 3];           // W2 @ [att_src2^T | att_dst2^T | Wg]
__device__ float  g_c2;                   // bias2 . Wg
__device__ float  g_out[N_GRAPHS];        // pool accumulator (recycled)
__device__ __align__(16) int g_deg[N_NODES];       // in-degree cursor (recycled)
__device__ __align__(16) int g_csr[N_NODES * ROW]; // padded rows: src per edge

// ---------------- CSR build: single atomic-append pass (deg pre-zeroed) -----
__global__ void k_scatter(const int* __restrict__ ei) {
    int e = (blockIdx.x * blockDim.x + threadIdx.x) * 4;
    if (e >= N_EDGES) return;
    int4 sv = *(const int4*)(ei + e);
    int4 dv = *(const int4*)(ei + N_EDGES + e);
    int p0 = atomicAdd(&g_deg[dv.x], 1);
    int p1 = atomicAdd(&g_deg[dv.y], 1);
    int p2 = atomicAdd(&g_deg[dv.z], 1);
    int p3 = atomicAdd(&g_deg[dv.w], 1);
    g_csr[dv.x * ROW + p0] = sv.x;
    g_csr[dv.y * ROW + p1] = sv.y;
    g_csr[dv.z * ROW + p2] = sv.z;
    g_csr[dv.w * ROW + p3] = sv.w;
}

// ---------------- GEMM1 + att1 fused (+ prep block): runs on forked stream --
__global__ __launch_bounds__(256) void k_gemm1(const float* __restrict__ x,
                                               const float* __restrict__ W,
                                               const float* __restrict__ att_src,
                                               const float* __restrict__ att_dst,
                                               const float* __restrict__ W2,
                                               const float* __restrict__ as2v,
                                               const float* __restrict__ ad2v,
                                               const float* __restrict__ Wg,
                                               const float* __restrict__ bias2) {
    if (blockIdx.x == GEMM_BLOCKS) {        // ---- prep branch (one block) ----
        int t = threadIdx.x;
        if (t < 192) {
            int c = t & 63, j = t >> 6;
            const float* v = (j == 0) ? as2v : (j == 1) ? ad2v : Wg;
            float s = 0.f;
            #pragma unroll 4
            for (int o = 0; o < 128; o++) s += W2[c * 128 + o] * v[o];
            g_M3[c * 3 + j] = s;
        } else if (t < 224) {
            int lane = t - 192;
            float s = 0.f;
            for (int o = lane; o < 128; o += 32) s += bias2[o] * Wg[o];
            #pragma unroll
            for (int o = 16; o; o >>= 1) s += __shfl_xor_sync(0xffffffffu, s, o);
            if (lane == 0) g_c2 = s;
        }
        return;
    }
    __shared__ float As[75 * 64];   // As[k][r] (A transposed)
    __shared__ float Bs[75 * 64];   // Bs[k][c]
    const int t = threadIdx.x;
    const int m0 = blockIdx.x * 64;
    for (int i = t; i < 75 * 64; i += 256) Bs[i] = W[i];
    for (int i = t; i < 64 * 75; i += 256) {
        int r = i / 75, k = i - r * 75;
        int gi = m0 + r;
        As[k * 64 + r] = (gi < N_NODES) ? x[gi * 75 + k] : 0.f;
    }
    __syncthreads();
    const int tx = t & 15, ty = t >> 4;
    const int r0 = ty * 4, c0 = tx * 4;
    float acc[4][4] = {};
    #pragma unroll 3
    for (int k = 0; k < 75; k++) {
        float4 av = *(const float4*)(As + k * 64 + r0);
        float4 bv = *(const float4*)(Bs + k * 64 + c0);
        float ar[4] = {av.x, av.y, av.z, av.w};
        float br[4] = {bv.x, bv.y, bv.z, bv.w};
        #pragma unroll
        for (int r = 0; r < 4; r++)
            #pragma unroll
            for (int c = 0; c < 4; c++) acc[r][c] += ar[r] * br[c];
    }
    // att1 epilogue: head h = tx>>1; thread pair (tx, tx^1) spans its 8 chans
    const int h = tx >> 1, half = tx & 1;
    float4 sv = *(const float4*)(att_src + h * 8 + half * 4);
    float4 dv = *(const float4*)(att_dst + h * 8 + half * 4);
    #pragma unroll
    for (int r = 0; r < 4; r++) {
        int gi = m0 + r0 + r;
        float ps = acc[r][0]*sv.x + acc[r][1]*sv.y + acc[r][2]*sv.z + acc[r][3]*sv.w;
        float pd = acc[r][0]*dv.x + acc[r][1]*dv.y + acc[r][2]*dv.z + acc[r][3]*dv.w;
        ps += __shfl_xor_sync(0xffffffffu, ps, 1);
        pd += __shfl_xor_sync(0xffffffffu, pd, 1);
        if (gi < N_NODES) {
            __nv_bfloat162 b0 = __floats2bfloat162_rn(acc[r][0], acc[r][1]);
            __nv_bfloat162 b1 = __floats2bfloat162_rn(acc[r][2], acc[r][3]);
            uint2 packed = make_uint2(*(unsigned*)&b0, *(unsigned*)&b1);
            *(uint2*)(g_h1b + gi * 32 + tx * 2) = packed;
            if (half == 0) {
                g_as1[gi * 8 + h] = ps * LOG2E;   // pre-scale for exp2
                g_ad1[gi * 8 + h] = pd * LOG2E;
            }
        }
    }
}

// ---------------- conv1 aggregation + conv2-score projection, fused ---------
// 8-lane group per node: lane l == head l, one uint4 (bf16x8) per edge.
// Self-loop seeded from registers; csr in int2 pairs; plain scalar FFMA
// (round-10 register profile: high occupancy beats deeper batching here).
__global__ void k_edge1(const float* __restrict__ bias1) {
    int w = (blockIdx.x * blockDim.x + threadIdx.x) >> 3;   // node id
    if (w >= N_NODES) return;
    int l = threadIdx.x & 7;                                 // head id
    float adst = g_ad1[w * 8 + l];
    // self-loop contribution (s == w), no csr involved
    float eaS = g_as1[w * 8 + l] + adst;
    eaS = fmaxf(eaS, NEG_SLOPE * eaS);
    float eeS = exp2f(eaS);
    uint4 rS = *(const uint4*)(g_h1b + w * 32 + l * 4);
    float2 p0 = __bfloat1622float2(*(__nv_bfloat162*)&rS.x);
    float2 p1 = __bfloat1622float2(*(__nv_bfloat162*)&rS.y);
    float2 p2 = __bfloat1622float2(*(__nv_bfloat162*)&rS.z);
    float2 p3 = __bfloat1622float2(*(__nv_bfloat162*)&rS.w);
    float c0 = eeS * p0.x, c1 = eeS * p0.y, c2 = eeS * p1.x, c3 = eeS * p1.y;
    float c4 = eeS * p2.x, c5 = eeS * p2.y, c6 = eeS * p3.x, c7 = eeS * p3.y;
    float den = eeS;
    int e0 = w * ROW, nE = g_deg[w];
    int e = 0;
    for (; e + 2 <= nE; e += 2) {
        int2 ss = *(const int2*)(g_csr + e0 + e);
        float aA = g_as1[ss.x * 8 + l];
        float aB = g_as1[ss.y * 8 + l];
        uint4 rA = *(const uint4*)(g_h1b + ss.x * 32 + l * 4);
        uint4 rB = *(const uint4*)(g_h1b + ss.y * 32 + l * 4);
        float eaA = aA + adst, eaB = aB + adst;
        eaA = fmaxf(eaA, NEG_SLOPE * eaA);
        eaB = fmaxf(eaB, NEG_SLOPE * eaB);
        float eeA = exp2f(eaA), eeB = exp2f(eaB);
        {
            float2 q0 = __bfloat1622float2(*(__nv_bfloat162*)&rA.x);
            float2 q1 = __bfloat1622float2(*(__nv_bfloat162*)&rA.y);
            float2 q2 = __bfloat1622float2(*(__nv_bfloat162*)&rA.z);
            float2 q3 = __bfloat1622float2(*(__nv_bfloat162*)&rA.w);
            c0 += eeA * q0.x; c1 += eeA * q0.y; c2 += eeA * q1.x; c3 += eeA * q1.y;
            c4 += eeA * q2.x; c5 += eeA * q2.y; c6 += eeA * q3.x; c7 += eeA * q3.y;
        }
        {
            float2 q0 = __bfloat1622float2(*(__nv_bfloat162*)&rB.x);
            float2 q1 = __bfloat1622float2(*(__nv_bfloat162*)&rB.y);
            float2 q2 = __bfloat1622float2(*(__nv_bfloat162*)&rB.z);
            float2 q3 = __bfloat1622float2(*(__nv_bfloat162*)&rB.w);
            c0 += eeB * q0.x; c1 += eeB * q0.y; c2 += eeB * q1.x; c3 += eeB * q1.y;
            c4 += eeB * q2.x; c5 += eeB * q2.y; c6 += eeB * q3.x; c7 += eeB * q3.y;
        }
        den += eeA + eeB;
    }
    if (e < nE) {
        int s = g_csr[e0 + e];
        float a = g_as1[s * 8 + l];
        uint4 r = *(const uint4*)(g_h1b + s * 32 + l * 4);
        float ea = a + adst;
        ea = fmaxf(ea, NEG_SLOPE * ea);
        float ee = exp2f(ea);
        float2 q0 = __bfloat1622float2(*(__nv_bfloat162*)&r.x);
        float2 q1 = __bfloat1622float2(*(__nv_bfloat162*)&r.y);
        float2 q2 = __bfloat1622float2(*(__nv_bfloat162*)&r.z);
        float2 q3 = __bfloat1622float2(*(__nv_bfloat162*)&r.w);
        c0 += ee * q0.x; c1 += ee * q0.y; c2 += ee * q1.x; c3 += ee * q1.y;
        c4 += ee * q2.x; c5 += ee * q2.y; c6 += ee * q3.x; c7 += ee * q3.y;
        den += ee;
    }
    float inv = 1.f / den;
    int co = l * 8;
    float4 b0 = *(const float4*)(bias1 + co);
    float4 b1 = *(const float4*)(bias1 + co + 4);
    float v[8];
    v[0] = c0 * inv + b0.x; v[1] = c1 * inv + b0.y;
    v[2] = c2 * inv + b0.z; v[3] = c3 * inv + b0.w;
    v[4] = c4 * inv + b1.x; v[5] = c5 * inv + b1.y;
    v[6] = c6 * inv + b1.z; v[7] = c7 * inv + b1.w;
    #pragma unroll
    for (int j = 0; j < 8; j++)
        v[j] = (v[j] > 0.f) ? v[j] : (__expf(v[j]) - 1.f);   // ELU
    // project x2 row chunk onto the 3 fused conv2 vectors
    float s0 = 0.f, s1 = 0.f, s2 = 0.f;
    #pragma unroll
    for (int j = 0; j < 8; j++) {
        s0 += v[j] * g_M3[(co + j) * 3 + 0];
        s1 += v[j] * g_M3[(co + j) * 3 + 1];
        s2 += v[j] * g_M3[(co + j) * 3 + 2];
    }
    #pragma unroll
    for (int o = 4; o; o >>= 1) {    // group-local reduce (offsets < 8)
        s0 += __shfl_xor_sync(0xffffffffu, s0, o);
        s1 += __shfl_xor_sync(0xffffffffu, s1, o);
        s2 += __shfl_xor_sync(0xffffffffu, s2, o);
    }
    if (l == 0) {
        g_ap2[w] = make_float2(s0 * LOG2E, s2);   // (as2*log2e, p)
        g_ad2[w] = s1 * LOG2E;
    }
}

// ---------------- conv2 aggregation + pool; resets deg for next call --------
__global__ void k_edge2(const int* __restrict__ batch) {
    int w = (blockIdx.x * blockDim.x + threadIdx.x) >> 3;
    if (w >= N_NODES) return;
    int l = threadIdx.x & 7;
    float adst = g_ad2[w];
    float num = 0.f, den = 0.f;
    float2 apW = g_ap2[w];
    if (l == 0) {            // self-loop
        float ea = apW.x + adst;
        ea = fmaxf(ea, NEG_SLOPE * ea);
        float ee = exp2f(ea);
        num = ee * apW.y;
        den = ee;
    }
    int e0 = w * ROW, e1 = e0 + g_deg[w];
    int e = e0 + l;
    for (; e + 8 < e1; e += 16) {
        int sA = g_csr[e], sB = g_csr[e + 8];
        float2 apA = g_ap2[sA];
        float2 apB = g_ap2[sB];
        float eaA = apA.x + adst;
        float eaB = apB.x + adst;
        eaA = fmaxf(eaA, NEG_SLOPE * eaA);
        eaB = fmaxf(eaB, NEG_SLOPE * eaB);
        float eeA = exp2f(eaA), eeB = exp2f(eaB);
        num += eeA * apA.y + eeB * apB.y;
        den += eeA + eeB;
    }
    if (e < e1) {
        int s = g_csr[e];
        float2 ap = g_ap2[s];
        float ea = ap.x + adst;
        ea = fmaxf(ea, NEG_SLOPE * ea);
        float ee = exp2f(ea);
        num += ee * ap.y;
        den += ee;
    }
    #pragma unroll
    for (int o = 4; o; o >>= 1) {    // group-local reduce (offsets < 8)
        num += __shfl_xor_sync(0xffffffffu, num, o);
        den += __shfl_xor_sync(0xffffffffu, den, o);
    }
    if (l == 0) {
        atomicAdd(g_out + batch[w], num / den + g_c2);
        g_deg[w] = 0;        // recycle: next call starts with deg == 0
    }
}

// ---------------- final: out = g_out + bg; reset g_out ----------------------
__global__ void k_final(float* __restrict__ out, const float* __restrict__ bg) {
    int g = threadIdx.x + blockIdx.x * blockDim.x;
    if (g < N_GRAPHS) {
        out[g] = g_out[g] + bg[0];
        g_out[g] = 0.f;      // recycle
    }
}

// ---------------- launch: scatter (main) || gemm1+prep (s2) -----------------
extern "C" void kernel_launch(void* const* d_in, const int* in_sizes, int n_in,
                              void* d_out, int out_size) {
    const float* x        = (const float*)d_in[0];
    const int*   ei       = (const int*)  d_in[1];
    const int*   batch    = (const int*)  d_in[2];
    const float* W1       = (const float*)d_in[3];
    const float* att_src1 = (const float*)d_in[4];
    const float* att_dst1 = (const float*)d_in[5];
    const float* bias1    = (const float*)d_in[6];
    const float* W2       = (const float*)d_in[7];
    const float* att_src2 = (const float*)d_in[8];
    const float* att_dst2 = (const float*)d_in[9];
    const float* bias2    = (const float*)d_in[10];
    const float* Wg       = (const float*)d_in[11];
    const float* bg       = (const float*)d_in[12];
    float* out = (float*)d_out;

    static cudaStream_t s2 = 0;
    static cudaEvent_t ev_fork = 0, ev_join = 0;
    if (!s2) {
        cudaStreamCreateWithFlags(&s2, cudaStreamNonBlocking);
        cudaEventCreateWithFlags(&ev_fork, cudaEventDisableTiming);
        cudaEventCreateWithFlags(&ev_join, cudaEventDisableTiming);
    }

    // fork: gemm1(+prep) on s2, CSR build on the launch stream
    cudaEventRecord(ev_fork, 0);
    cudaStreamWaitEvent(s2, ev_fork, 0);
    k_gemm1<<<GEMM_BLOCKS + 1, 256, 0, s2>>>(x, W1, att_src1, att_dst1,
                                             W2, att_src2, att_dst2, Wg, bias2);
    cudaEventRecord(ev_join, s2);

    k_scatter<<<(N_EDGES / 4 + 255) / 256, 256>>>(ei);

    cudaStreamWaitEvent(0, ev_join, 0);
    k_edge1<<<(N_NODES * 8 + 255) / 256, 256>>>(bias1);
    k_edge2<<<(N_NODES * 8 + 255) / 256, 256>>>(batch);
    k_final<<<2, 256>>>(out, bg);
}

// round 14
// speedup vs baseline: 1.3281x; 1.2070x over previous
#include <cuda_runtime.h>
#include <cuda_bf16.h>

#define N_NODES 100000
#define N_EDGES 1600000
#define N_GRAPHS 512
#define NEG_SLOPE 0.2f
#define ROW 64                         // padded CSR row size (max in-degree)
#define LOG2E 1.4426950408889634f
#define GEMM_BLOCKS ((N_NODES + 63) / 64)        // 1563
#define SCAT_BLOCKS ((N_EDGES / 4 + 255) / 256)  // 1563 edge blocks

// ---------------- scratch (static device globals; no allocs allowed) --------
// g_deg is zero at module load and re-zeroed by k_edge2 each call, so no
// init pass is needed and every kernel_launch call is state-neutral.
__device__ __align__(16) __nv_bfloat162 g_h1b[N_NODES * 32]; // h1 messages, bf16
__device__ __align__(16) float  g_as1[N_NODES * 8];   // conv1 att src scores (*log2e)
__device__ __align__(16) float  g_ad1[N_NODES * 8];   // conv1 att dst scores (*log2e)
__device__ float2 g_ap2[N_NODES];         // (as2*log2e, p=h2.Wg) per node
__device__ float  g_ad2[N_NODES];         // ad2*log2e
__device__ float  g_M3[64 * 3];           // W2 @ [att_src2^T | att_dst2^T | Wg]
__device__ float  g_c2;                   // bias2 . Wg
__device__ __align__(16) int g_deg[N_NODES];       // in-degree cursor (recycled)
__device__ __align__(16) int g_csr[N_NODES * ROW]; // padded rows: src per edge

// ---------------- CSR build + output seed (out = bg) ------------------------
__global__ void k_scatter(const int* __restrict__ ei,
                          float* __restrict__ out, const float* __restrict__ bg) {
    if (blockIdx.x == SCAT_BLOCKS) {     // seed the pool output with bg
        float b = bg[0];
        int g = threadIdx.x;
        out[g] = b;
        out[g + 256] = b;
        return;
    }
    int e = (blockIdx.x * blockDim.x + threadIdx.x) * 4;
    if (e >= N_EDGES) return;
    int4 sv = *(const int4*)(ei + e);
    int4 dv = *(const int4*)(ei + N_EDGES + e);
    int p0 = atomicAdd(&g_deg[dv.x], 1);
    int p1 = atomicAdd(&g_deg[dv.y], 1);
    int p2 = atomicAdd(&g_deg[dv.z], 1);
    int p3 = atomicAdd(&g_deg[dv.w], 1);
    g_csr[dv.x * ROW + p0] = sv.x;
    g_csr[dv.y * ROW + p1] = sv.y;
    g_csr[dv.z * ROW + p2] = sv.z;
    g_csr[dv.w * ROW + p3] = sv.w;
}

// ---------------- GEMM1 + att1 fused (+ prep block): runs on forked stream --
__global__ __launch_bounds__(256) void k_gemm1(const float* __restrict__ x,
                                               const float* __restrict__ W,
                                               const float* __restrict__ att_src,
                                               const float* __restrict__ att_dst,
                                               const float* __restrict__ W2,
                                               const float* __restrict__ as2v,
                                               const float* __restrict__ ad2v,
                                               const float* __restrict__ Wg,
                                               const float* __restrict__ bias2) {
    if (blockIdx.x == GEMM_BLOCKS) {        // ---- prep branch (one block) ----
        int t = threadIdx.x;
        if (t < 192) {
            int c = t & 63, j = t >> 6;
            const float* v = (j == 0) ? as2v : (j == 1) ? ad2v : Wg;
            float s = 0.f;
            #pragma unroll 4
            for (int o = 0; o < 128; o++) s += W2[c * 128 + o] * v[o];
            g_M3[c * 3 + j] = s;
        } else if (t < 224) {
            int lane = t - 192;
            float s = 0.f;
            for (int o = lane; o < 128; o += 32) s += bias2[o] * Wg[o];
            #pragma unroll
            for (int o = 16; o; o >>= 1) s += __shfl_xor_sync(0xffffffffu, s, o);
            if (lane == 0) g_c2 = s;
        }
        return;
    }
    __shared__ float As[75 * 64];   // As[k][r] (A transposed)
    __shared__ float Bs[75 * 64];   // Bs[k][c]
    const int t = threadIdx.x;
    const int m0 = blockIdx.x * 64;
    for (int i = t; i < 75 * 64; i += 256) Bs[i] = W[i];
    for (int i = t; i < 64 * 75; i += 256) {
        int r = i / 75, k = i - r * 75;
        int gi = m0 + r;
        As[k * 64 + r] = (gi < N_NODES) ? x[gi * 75 + k] : 0.f;
    }
    __syncthreads();
    const int tx = t & 15, ty = t >> 4;
    const int r0 = ty * 4, c0 = tx * 4;
    float acc[4][4] = {};
    #pragma unroll 3
    for (int k = 0; k < 75; k++) {
        float4 av = *(const float4*)(As + k * 64 + r0);
        float4 bv = *(const float4*)(Bs + k * 64 + c0);
        float ar[4] = {av.x, av.y, av.z, av.w};
        float br[4] = {bv.x, bv.y, bv.z, bv.w};
        #pragma unroll
        for (int r = 0; r < 4; r++)
            #pragma unroll
            for (int c = 0; c < 4; c++) acc[r][c] += ar[r] * br[c];
    }
    // att1 epilogue: head h = tx>>1; thread pair (tx, tx^1) spans its 8 chans
    const int h = tx >> 1, half = tx & 1;
    float4 sv = *(const float4*)(att_src + h * 8 + half * 4);
    float4 dv = *(const float4*)(att_dst + h * 8 + half * 4);
    #pragma unroll
    for (int r = 0; r < 4; r++) {
        int gi = m0 + r0 + r;
        float ps = acc[r][0]*sv.x + acc[r][1]*sv.y + acc[r][2]*sv.z + acc[r][3]*sv.w;
        float pd = acc[r][0]*dv.x + acc[r][1]*dv.y + acc[r][2]*dv.z + acc[r][3]*dv.w;
        ps += __shfl_xor_sync(0xffffffffu, ps, 1);
        pd += __shfl_xor_sync(0xffffffffu, pd, 1);
        if (gi < N_NODES) {
            __nv_bfloat162 b0 = __floats2bfloat162_rn(acc[r][0], acc[r][1]);
            __nv_bfloat162 b1 = __floats2bfloat162_rn(acc[r][2], acc[r][3]);
            uint2 packed = make_uint2(*(unsigned*)&b0, *(unsigned*)&b1);
            *(uint2*)(g_h1b + gi * 32 + tx * 2) = packed;
            if (half == 0) {
                g_as1[gi * 8 + h] = ps * LOG2E;   // pre-scale for exp2
                g_ad1[gi * 8 + h] = pd * LOG2E;
            }
        }
    }
}

// ---------------- conv1 aggregation + conv2-score projection, fused ---------
// 8-lane group per node: lane l == head l, one uint4 (bf16x8) per edge.
__global__ void k_edge1(const float* __restrict__ bias1) {
    int w = (blockIdx.x * blockDim.x + threadIdx.x) >> 3;   // node id
    if (w >= N_NODES) return;
    int l = threadIdx.x & 7;                                 // head id
    float adst = g_ad1[w * 8 + l];
    // self-loop contribution (s == w), no csr involved
    float eaS = g_as1[w * 8 + l] + adst;
    eaS = fmaxf(eaS, NEG_SLOPE * eaS);
    float eeS = exp2f(eaS);
    uint4 rS = *(const uint4*)(g_h1b + w * 32 + l * 4);
    float2 p0 = __bfloat1622float2(*(__nv_bfloat162*)&rS.x);
    float2 p1 = __bfloat1622float2(*(__nv_bfloat162*)&rS.y);
    float2 p2 = __bfloat1622float2(*(__nv_bfloat162*)&rS.z);
    float2 p3 = __bfloat1622float2(*(__nv_bfloat162*)&rS.w);
    float c0 = eeS * p0.x, c1 = eeS * p0.y, c2 = eeS * p1.x, c3 = eeS * p1.y;
    float c4 = eeS * p2.x, c5 = eeS * p2.y, c6 = eeS * p3.x, c7 = eeS * p3.y;
    float den = eeS;
    int e0 = w * ROW, nE = g_deg[w];
    int e = 0;
    for (; e + 2 <= nE; e += 2) {
        int2 ss = *(const int2*)(g_csr + e0 + e);
        float aA = g_as1[ss.x * 8 + l];
        float aB = g_as1[ss.y * 8 + l];
        uint4 rA = *(const uint4*)(g_h1b + ss.x * 32 + l * 4);
        uint4 rB = *(const uint4*)(g_h1b + ss.y * 32 + l * 4);
        float eaA = aA + adst, eaB = aB + adst;
        eaA = fmaxf(eaA, NEG_SLOPE * eaA);
        eaB = fmaxf(eaB, NEG_SLOPE * eaB);
        float eeA = exp2f(eaA), eeB = exp2f(eaB);
        {
            float2 q0 = __bfloat1622float2(*(__nv_bfloat162*)&rA.x);
            float2 q1 = __bfloat1622float2(*(__nv_bfloat162*)&rA.y);
            float2 q2 = __bfloat1622float2(*(__nv_bfloat162*)&rA.z);
            float2 q3 = __bfloat1622float2(*(__nv_bfloat162*)&rA.w);
            c0 += eeA * q0.x; c1 += eeA * q0.y; c2 += eeA * q1.x; c3 += eeA * q1.y;
            c4 += eeA * q2.x; c5 += eeA * q2.y; c6 += eeA * q3.x; c7 += eeA * q3.y;
        }
        {
            float2 q0 = __bfloat1622float2(*(__nv_bfloat162*)&rB.x);
            float2 q1 = __bfloat1622float2(*(__nv_bfloat162*)&rB.y);
            float2 q2 = __bfloat1622float2(*(__nv_bfloat162*)&rB.z);
            float2 q3 = __bfloat1622float2(*(__nv_bfloat162*)&rB.w);
            c0 += eeB * q0.x; c1 += eeB * q0.y; c2 += eeB * q1.x; c3 += eeB * q1.y;
            c4 += eeB * q2.x; c5 += eeB * q2.y; c6 += eeB * q3.x; c7 += eeB * q3.y;
        }
        den += eeA + eeB;
    }
    if (e < nE) {
        int s = g_csr[e0 + e];
        float a = g_as1[s * 8 + l];
        uint4 r = *(const uint4*)(g_h1b + s * 32 + l * 4);
        float ea = a + adst;
        ea = fmaxf(ea, NEG_SLOPE * ea);
        float ee = exp2f(ea);
        float2 q0 = __bfloat1622float2(*(__nv_bfloat162*)&r.x);
        float2 q1 = __bfloat1622float2(*(__nv_bfloat162*)&r.y);
        float2 q2 = __bfloat1622float2(*(__nv_bfloat162*)&r.z);
        float2 q3 = __bfloat1622float2(*(__nv_bfloat162*)&r.w);
        c0 += ee * q0.x; c1 += ee * q0.y; c2 += ee * q1.x; c3 += ee * q1.y;
        c4 += ee * q2.x; c5 += ee * q2.y; c6 += ee * q3.x; c7 += ee * q3.y;
        den += ee;
    }
    float inv = 1.f / den;
    int co = l * 8;
    float4 b0 = *(const float4*)(bias1 + co);
    float4 b1 = *(const float4*)(bias1 + co + 4);
    float v[8];
    v[0] = c0 * inv + b0.x; v[1] = c1 * inv + b0.y;
    v[2] = c2 * inv + b0.z; v[3] = c3 * inv + b0.w;
    v[4] = c4 * inv + b1.x; v[5] = c5 * inv + b1.y;
    v[6] = c6 * inv + b1.z; v[7] = c7 * inv + b1.w;
    #pragma unroll
    for (int j = 0; j < 8; j++)
        v[j] = (v[j] > 0.f) ? v[j] : (__expf(v[j]) - 1.f);   // ELU
    // project x2 row chunk onto the 3 fused conv2 vectors
    float s0 = 0.f, s1 = 0.f, s2 = 0.f;
    #pragma unroll
    for (int j = 0; j < 8; j++) {
        s0 += v[j] * g_M3[(co + j) * 3 + 0];
        s1 += v[j] * g_M3[(co + j) * 3 + 1];
        s2 += v[j] * g_M3[(co + j) * 3 + 2];
    }
    #pragma unroll
    for (int o = 4; o; o >>= 1) {    // group-local reduce (offsets < 8)
        s0 += __shfl_xor_sync(0xffffffffu, s0, o);
        s1 += __shfl_xor_sync(0xffffffffu, s1, o);
        s2 += __shfl_xor_sync(0xffffffffu, s2, o);
    }
    if (l == 0) {
        g_ap2[w] = make_float2(s0 * LOG2E, s2);   // (as2*log2e, p)
        g_ad2[w] = s1 * LOG2E;
    }
}

// ---------------- conv2 aggregation + block-segmented pool ------------------
// 8-lane group per node. Block covers 32 consecutive (batch-sorted) nodes:
// group-reduce -> smem (graph,val) pairs -> key-guarded suffix scan in warp 0
// -> atomicAdd ONLY at segment heads (kills same-address atomic contention).
// Also resets g_deg for the next call. Grid is exact: 100000*8/256 = 3125.
__global__ void k_edge2(const int* __restrict__ batch,
                        float* __restrict__ out) {
    __shared__ int   sgid[32];
    __shared__ float sval[32];
    int w = (blockIdx.x * blockDim.x + threadIdx.x) >> 3;
    int l = threadIdx.x & 7;
    int grp = threadIdx.x >> 3;       // 0..31 group within block
    float adst = g_ad2[w];
    float num = 0.f, den = 0.f;
    float2 apW = g_ap2[w];
    if (l == 0) {            // self-loop
        float ea = apW.x + adst;
        ea = fmaxf(ea, NEG_SLOPE * ea);
        float ee = exp2f(ea);
        num = ee * apW.y;
        den = ee;
    }
    int e0 = w * ROW, e1 = e0 + g_deg[w];
    int e = e0 + l;
    for (; e + 8 < e1; e += 16) {
        int sA = g_csr[e], sB = g_csr[e + 8];
        float2 apA = g_ap2[sA];
        float2 apB = g_ap2[sB];
        float eaA = apA.x + adst;
        float eaB = apB.x + adst;
        eaA = fmaxf(eaA, NEG_SLOPE * eaA);
        eaB = fmaxf(eaB, NEG_SLOPE * eaB);
        float eeA = exp2f(eaA), eeB = exp2f(eaB);
        num += eeA * apA.y + eeB * apB.y;
        den += eeA + eeB;
    }
    if (e < e1) {
        int s = g_csr[e];
        float2 ap = g_ap2[s];
        float ea = ap.x + adst;
        ea = fmaxf(ea, NEG_SLOPE * ea);
        float ee = exp2f(ea);
        num += ee * ap.y;
        den += ee;
    }
    #pragma unroll
    for (int o = 4; o; o >>= 1) {    // group-local reduce (offsets < 8)
        num += __shfl_xor_sync(0xffffffffu, num, o);
        den += __shfl_xor_sync(0xffffffffu, den, o);
    }
    if (l == 0) {
        sgid[grp] = batch[w];
        sval[grp] = num / den + g_c2;
        g_deg[w] = 0;                // recycle: next call starts with deg == 0
    }
    __syncthreads();
    if (threadIdx.x < 32) {
        int   b = sgid[threadIdx.x];
        float v = sval[threadIdx.x];
        // key-guarded Kogge-Stone suffix sum over sorted keys
        #pragma unroll
        for (int o = 1; o < 32; o <<= 1) {
            float u  = __shfl_down_sync(0xffffffffu, v, o);
            int   bu = __shfl_down_sync(0xffffffffu, b, o);
            if (threadIdx.x + o < 32 && bu == b) v += u;
        }
        int bprev = __shfl_up_sync(0xffffffffu, b, 1);
        if (threadIdx.x == 0 || bprev != b)   // segment head
            atomicAdd(out + b, v);
    }
}

// ---------------- launch: scatter+seed (main) || gemm1+prep (s2) ------------
extern "C" void kernel_launch(void* const* d_in, const int* in_sizes, int n_in,
                              void* d_out, int out_size) {
    const float* x        = (const float*)d_in[0];
    const int*   ei       = (const int*)  d_in[1];
    const int*   batch    = (const int*)  d_in[2];
    const float* W1       = (const float*)d_in[3];
    const float* att_src1 = (const float*)d_in[4];
    const float* att_dst1 = (const float*)d_in[5];
    const float* bias1    = (const float*)d_in[6];
    const float* W2       = (const float*)d_in[7];
    const float* att_src2 = (const float*)d_in[8];
    const float* att_dst2 = (const float*)d_in[9];
    const float* bias2    = (const float*)d_in[10];
    const float* Wg       = (const float*)d_in[11];
    const float* bg       = (const float*)d_in[12];
    float* out = (float*)d_out;

    static cudaStream_t s2 = 0;
    static cudaEvent_t ev_fork = 0, ev_join = 0;
    if (!s2) {
        cudaStreamCreateWithFlags(&s2, cudaStreamNonBlocking);
        cudaEventCreateWithFlags(&ev_fork, cudaEventDisableTiming);
        cudaEventCreateWithFlags(&ev_join, cudaEventDisableTiming);
    }

    // fork: gemm1(+prep) on s2, CSR build (+ output seed) on the launch stream
    cudaEventRecord(ev_fork, 0);
    cudaStreamWaitEvent(s2, ev_fork, 0);
    k_gemm1<<<GEMM_BLOCKS + 1, 256, 0, s2>>>(x, W1, att_src1, att_dst1,
                                             W2, att_src2, att_dst2, Wg, bias2);
    cudaEventRecord(ev_join, s2);

    k_scatter<<<SCAT_BLOCKS + 1, 256>>>(ei, out, bg);

    cudaStreamWaitEvent(0, ev_join, 0);
    k_edge1<<<(N_NODES * 8 + 255) / 256, 256>>>(bias1);
    k_edge2<<<(N_NODES * 8 + 255) / 256, 256>>>(batch, out);
}

// round 15
// speedup vs baseline: 1.3977x; 1.0524x over previous
#include <cuda_runtime.h>
#include <cuda_bf16.h>

#define N_NODES 100000
#define N_EDGES 1600000
#define N_GRAPHS 512
#define NEG_SLOPE 0.2f
#define ROW 64                         // padded CSR row size (max in-degree)
#define LOG2E 1.4426950408889634f
#define AS 68                          // As row stride (bank-conflict pad)
#define GEMM_BLOCKS ((N_NODES + 63) / 64)        // 1563
#define SCAT_BLOCKS ((N_EDGES / 4 + 255) / 256)  // 1563 edge blocks

// ---------------- scratch (static device globals; no allocs allowed) --------
// g_deg is zero at module load and re-zeroed by k_edge2 each call, so no
// init pass is needed and every kernel_launch call is state-neutral.
__device__ __align__(16) __nv_bfloat162 g_h1b[N_NODES * 32]; // h1 messages, bf16
__device__ __align__(16) float  g_as1[N_NODES * 8];   // conv1 att src scores (*log2e)
__device__ __align__(16) float  g_ad1[N_NODES * 8];   // conv1 att dst scores (*log2e)
__device__ float2 g_ap2[N_NODES];         // (as2*log2e, p=h2.Wg) per node
__device__ float  g_ad2[N_NODES];         // ad2*log2e
__device__ float  g_M3[64 * 3];           // W2 @ [att_src2^T | att_dst2^T | Wg]
__device__ float  g_c2;                   // bias2 . Wg
__device__ __align__(16) int g_deg[N_NODES];       // in-degree cursor (recycled)
__device__ __align__(16) int g_csr[N_NODES * ROW]; // padded rows: src per edge

// ---------------- CSR build + output seed (out = bg) ------------------------
__global__ void k_scatter(const int* __restrict__ ei,
                          float* __restrict__ out, const float* __restrict__ bg) {
    if (blockIdx.x == SCAT_BLOCKS) {     // seed the pool output with bg
        float b = bg[0];
        int g = threadIdx.x;
        out[g] = b;
        out[g + 256] = b;
        return;
    }
    int e = (blockIdx.x * blockDim.x + threadIdx.x) * 4;
    if (e >= N_EDGES) return;
    int4 sv = *(const int4*)(ei + e);
    int4 dv = *(const int4*)(ei + N_EDGES + e);
    int p0 = atomicAdd(&g_deg[dv.x], 1);
    int p1 = atomicAdd(&g_deg[dv.y], 1);
    int p2 = atomicAdd(&g_deg[dv.z], 1);
    int p3 = atomicAdd(&g_deg[dv.w], 1);
    g_csr[dv.x * ROW + p0] = sv.x;
    g_csr[dv.y * ROW + p1] = sv.y;
    g_csr[dv.z * ROW + p2] = sv.z;
    g_csr[dv.w * ROW + p3] = sv.w;
}

// ---------------- GEMM1 + att1 fused (+ prep block): runs on forked stream --
// As padded to stride 68: fill-phase STS conflicts drop 32-way -> 4-way.
__global__ __launch_bounds__(256) void k_gemm1(const float* __restrict__ x,
                                               const float* __restrict__ W,
                                               const float* __restrict__ att_src,
                                               const float* __restrict__ att_dst,
                                               const float* __restrict__ W2,
                                               const float* __restrict__ as2v,
                                               const float* __restrict__ ad2v,
                                               const float* __restrict__ Wg,
                                               const float* __restrict__ bias2) {
    if (blockIdx.x == GEMM_BLOCKS) {        // ---- prep branch (one block) ----
        int t = threadIdx.x;
        if (t < 192) {
            int c = t & 63, j = t >> 6;
            const float* v = (j == 0) ? as2v : (j == 1) ? ad2v : Wg;
            float s = 0.f;
            #pragma unroll 4
            for (int o = 0; o < 128; o++) s += W2[c * 128 + o] * v[o];
            g_M3[c * 3 + j] = s;
        } else if (t < 224) {
            int lane = t - 192;
            float s = 0.f;
            for (int o = lane; o < 128; o += 32) s += bias2[o] * Wg[o];
            #pragma unroll
            for (int o = 16; o; o >>= 1) s += __shfl_xor_sync(0xffffffffu, s, o);
            if (lane == 0) g_c2 = s;
        }
        return;
    }
    __shared__ float As[75 * AS];   // As[k][r] (A transposed, padded rows)
    __shared__ float Bs[75 * 64];   // Bs[k][c]
    const int t = threadIdx.x;
    const int m0 = blockIdx.x * 64;
    for (int i = t; i < 75 * 64; i += 256) Bs[i] = W[i];
    for (int i = t; i < 64 * 75; i += 256) {
        int r = i / 75, k = i - r * 75;
        int gi = m0 + r;
        As[k * AS + r] = (gi < N_NODES) ? x[gi * 75 + k] : 0.f;
    }
    __syncthreads();
    const int tx = t & 15, ty = t >> 4;
    const int r0 = ty * 4, c0 = tx * 4;
    float acc[4][4] = {};
    #pragma unroll 3
    for (int k = 0; k < 75; k++) {
        float4 av = *(const float4*)(As + k * AS + r0);
        float4 bv = *(const float4*)(Bs + k * 64 + c0);
        float ar[4] = {av.x, av.y, av.z, av.w};
        float br[4] = {bv.x, bv.y, bv.z, bv.w};
        #pragma unroll
        for (int r = 0; r < 4; r++)
            #pragma unroll
            for (int c = 0; c < 4; c++) acc[r][c] += ar[r] * br[c];
    }
    // att1 epilogue: head h = tx>>1; thread pair (tx, tx^1) spans its 8 chans
    const int h = tx >> 1, half = tx & 1;
    float4 sv = *(const float4*)(att_src + h * 8 + half * 4);
    float4 dv = *(const float4*)(att_dst + h * 8 + half * 4);
    #pragma unroll
    for (int r = 0; r < 4; r++) {
        int gi = m0 + r0 + r;
        float ps = acc[r][0]*sv.x + acc[r][1]*sv.y + acc[r][2]*sv.z + acc[r][3]*sv.w;
        float pd = acc[r][0]*dv.x + acc[r][1]*dv.y + acc[r][2]*dv.z + acc[r][3]*dv.w;
        ps += __shfl_xor_sync(0xffffffffu, ps, 1);
        pd += __shfl_xor_sync(0xffffffffu, pd, 1);
        if (gi < N_NODES) {
            __nv_bfloat162 b0 = __floats2bfloat162_rn(acc[r][0], acc[r][1]);
            __nv_bfloat162 b1 = __floats2bfloat162_rn(acc[r][2], acc[r][3]);
            uint2 packed = make_uint2(*(unsigned*)&b0, *(unsigned*)&b1);
            *(uint2*)(g_h1b + gi * 32 + tx * 2) = packed;
            if (half == 0) {
                g_as1[gi * 8 + h] = ps * LOG2E;   // pre-scale for exp2
                g_ad1[gi * 8 + h] = pd * LOG2E;
            }
        }
    }
}

// ---------------- conv1 aggregation + conv2-score projection, fused ---------
// 8-lane group per node: lane l == head l, one uint4 (bf16x8) per edge.
__global__ void k_edge1(const float* __restrict__ bias1) {
    int w = (blockIdx.x * blockDim.x + threadIdx.x) >> 3;   // node id
    if (w >= N_NODES) return;
    int l = threadIdx.x & 7;                                 // head id
    float adst = g_ad1[w * 8 + l];
    // self-loop contribution (s == w), no csr involved
    float eaS = g_as1[w * 8 + l] + adst;
    eaS = fmaxf(eaS, NEG_SLOPE * eaS);
    float eeS = exp2f(eaS);
    uint4 rS = *(const uint4*)(g_h1b + w * 32 + l * 4);
    float2 p0 = __bfloat1622float2(*(__nv_bfloat162*)&rS.x);
    float2 p1 = __bfloat1622float2(*(__nv_bfloat162*)&rS.y);
    float2 p2 = __bfloat1622float2(*(__nv_bfloat162*)&rS.z);
    float2 p3 = __bfloat1622float2(*(__nv_bfloat162*)&rS.w);
    float c0 = eeS * p0.x, c1 = eeS * p0.y, c2 = eeS * p1.x, c3 = eeS * p1.y;
    float c4 = eeS * p2.x, c5 = eeS * p2.y, c6 = eeS * p3.x, c7 = eeS * p3.y;
    float den = eeS;
    int e0 = w * ROW, nE = g_deg[w];
    int e = 0;
    for (; e + 2 <= nE; e += 2) {
        int2 ss = *(const int2*)(g_csr + e0 + e);
        float aA = g_as1[ss.x * 8 + l];
        float aB = g_as1[ss.y * 8 + l];
        uint4 rA = *(const uint4*)(g_h1b + ss.x * 32 + l * 4);
        uint4 rB = *(const uint4*)(g_h1b + ss.y * 32 + l * 4);
        float eaA = aA + adst, eaB = aB + adst;
        eaA = fmaxf(eaA, NEG_SLOPE * eaA);
        eaB = fmaxf(eaB, NEG_SLOPE * eaB);
        float eeA = exp2f(eaA), eeB = exp2f(eaB);
        {
            float2 q0 = __bfloat1622float2(*(__nv_bfloat162*)&rA.x);
            float2 q1 = __bfloat1622float2(*(__nv_bfloat162*)&rA.y);
            float2 q2 = __bfloat1622float2(*(__nv_bfloat162*)&rA.z);
            float2 q3 = __bfloat1622float2(*(__nv_bfloat162*)&rA.w);
            c0 += eeA * q0.x; c1 += eeA * q0.y; c2 += eeA * q1.x; c3 += eeA * q1.y;
            c4 += eeA * q2.x; c5 += eeA * q2.y; c6 += eeA * q3.x; c7 += eeA * q3.y;
        }
        {
            float2 q0 = __bfloat1622float2(*(__nv_bfloat162*)&rB.x);
            float2 q1 = __bfloat1622float2(*(__nv_bfloat162*)&rB.y);
            float2 q2 = __bfloat1622float2(*(__nv_bfloat162*)&rB.z);
            float2 q3 = __bfloat1622float2(*(__nv_bfloat162*)&rB.w);
            c0 += eeB * q0.x; c1 += eeB * q0.y; c2 += eeB * q1.x; c3 += eeB * q1.y;
            c4 += eeB * q2.x; c5 += eeB * q2.y; c6 += eeB * q3.x; c7 += eeB * q3.y;
        }
        den += eeA + eeB;
    }
    if (e < nE) {
        int s = g_csr[e0 + e];
        float a = g_as1[s * 8 + l];
        uint4 r = *(const uint4*)(g_h1b + s * 32 + l * 4);
        float ea = a + adst;
        ea = fmaxf(ea, NEG_SLOPE * ea);
        float ee = exp2f(ea);
        float2 q0 = __bfloat1622float2(*(__nv_bfloat162*)&r.x);
        float2 q1 = __bfloat1622float2(*(__nv_bfloat162*)&r.y);
        float2 q2 = __bfloat1622float2(*(__nv_bfloat162*)&r.z);
        float2 q3 = __bfloat1622float2(*(__nv_bfloat162*)&r.w);
        c0 += ee * q0.x; c1 += ee * q0.y; c2 += ee * q1.x; c3 += ee * q1.y;
        c4 += ee * q2.x; c5 += ee * q2.y; c6 += ee * q3.x; c7 += ee * q3.y;
        den += ee;
    }
    float inv = 1.f / den;
    int co = l * 8;
    float4 b0 = *(const float4*)(bias1 + co);
    float4 b1 = *(const float4*)(bias1 + co + 4);
    float v[8];
    v[0] = c0 * inv + b0.x; v[1] = c1 * inv + b0.y;
    v[2] = c2 * inv + b0.z; v[3] = c3 * inv + b0.w;
    v[4] = c4 * inv + b1.x; v[5] = c5 * inv + b1.y;
    v[6] = c6 * inv + b1.z; v[7] = c7 * inv + b1.w;
    #pragma unroll
    for (int j = 0; j < 8; j++)
        v[j] = (v[j] > 0.f) ? v[j] : (__expf(v[j]) - 1.f);   // ELU
    // project x2 row chunk onto the 3 fused conv2 vectors
    float s0 = 0.f, s1 = 0.f, s2 = 0.f;
    #pragma unroll
    for (int j = 0; j < 8; j++) {
        s0 += v[j] * g_M3[(co + j) * 3 + 0];
        s1 += v[j] * g_M3[(co + j) * 3 + 1];
        s2 += v[j] * g_M3[(co + j) * 3 + 2];
    }
    #pragma unroll
    for (int o = 4; o; o >>= 1) {    // group-local reduce (offsets < 8)
        s0 += __shfl_xor_sync(0xffffffffu, s0, o);
        s1 += __shfl_xor_sync(0xffffffffu, s1, o);
        s2 += __shfl_xor_sync(0xffffffffu, s2, o);
    }
    if (l == 0) {
        g_ap2[w] = make_float2(s0 * LOG2E, s2);   // (as2*log2e, p)
        g_ad2[w] = s1 * LOG2E;
    }
}

// ---------------- conv2 aggregation + block-segmented pool ------------------
// 8-lane group per node. Block covers 32 consecutive (batch-sorted) nodes:
// group-reduce -> smem (graph,val) pairs -> key-guarded suffix scan in warp 0
// -> atomicAdd ONLY at segment heads. Resets g_deg for the next call.
__global__ void k_edge2(const int* __restrict__ batch,
                        float* __restrict__ out) {
    __shared__ int   sgid[32];
    __shared__ float sval[32];
    int w = (blockIdx.x * blockDim.x + threadIdx.x) >> 3;
    int l = threadIdx.x & 7;
    int grp = threadIdx.x >> 3;       // 0..31 group within block
    int bw = batch[w];                // prefetch (broadcast within group)
    float adst = g_ad2[w];
    float num = 0.f, den = 0.f;
    float2 apW = g_ap2[w];
    if (l == 0) {            // self-loop
        float ea = apW.x + adst;
        ea = fmaxf(ea, NEG_SLOPE * ea);
        float ee = exp2f(ea);
        num = ee * apW.y;
        den = ee;
    }
    int e0 = w * ROW, e1 = e0 + g_deg[w];
    int e = e0 + l;
    for (; e + 8 < e1; e += 16) {
        int sA = g_csr[e], sB = g_csr[e + 8];
        float2 apA = g_ap2[sA];
        float2 apB = g_ap2[sB];
        float eaA = apA.x + adst;
        float eaB = apB.x + adst;
        eaA = fmaxf(eaA, NEG_SLOPE * eaA);
        eaB = fmaxf(eaB, NEG_SLOPE * eaB);
        float eeA = exp2f(eaA), eeB = exp2f(eaB);
        num += eeA * apA.y + eeB * apB.y;
        den += eeA + eeB;
    }
    if (e < e1) {
        int s = g_csr[e];
        float2 ap = g_ap2[s];
        float ea = ap.x + adst;
        ea = fmaxf(ea, NEG_SLOPE * ea);
        float ee = exp2f(ea);
        num += ee * ap.y;
        den += ee;
    }
    #pragma unroll
    for (int o = 4; o; o >>= 1) {    // group-local reduce (offsets < 8)
        num += __shfl_xor_sync(0xffffffffu, num, o);
        den += __shfl_xor_sync(0xffffffffu, den, o);
    }
    if (l == 0) {
        sgid[grp] = bw;
        sval[grp] = num / den + g_c2;
        g_deg[w] = 0;                // recycle: next call starts with deg == 0
    }
    __syncthreads();
    if (threadIdx.x < 32) {
        int   b = sgid[threadIdx.x];
        float v = sval[threadIdx.x];
        // key-guarded Kogge-Stone suffix sum over sorted keys
        #pragma unroll
        for (int o = 1; o < 32; o <<= 1) {
            float u  = __shfl_down_sync(0xffffffffu, v, o);
            int   bu = __shfl_down_sync(0xffffffffu, b, o);
            if (threadIdx.x + o < 32 && bu == b) v += u;
        }
        int bprev = __shfl_up_sync(0xffffffffu, b, 1);
        if (threadIdx.x == 0 || bprev != b)   // segment head
            atomicAdd(out + b, v);
    }
}

// ---------------- launch: scatter+seed (main) || gemm1+prep (s2) ------------
extern "C" void kernel_launch(void* const* d_in, const int* in_sizes, int n_in,
                              void* d_out, int out_size) {
    const float* x        = (const float*)d_in[0];
    const int*   ei       = (const int*)  d_in[1];
    const int*   batch    = (const int*)  d_in[2];
    const float* W1       = (const float*)d_in[3];
    const float* att_src1 = (const float*)d_in[4];
    const float* att_dst1 = (const float*)d_in[5];
    const float* bias1    = (const float*)d_in[6];
    const float* W2       = (const float*)d_in[7];
    const float* att_src2 = (const float*)d_in[8];
    const float* att_dst2 = (const float*)d_in[9];
    const float* bias2    = (const float*)d_in[10];
    const float* Wg       = (const float*)d_in[11];
    const float* bg       = (const float*)d_in[12];
    float* out = (float*)d_out;

    static cudaStream_t s2 = 0;
    static cudaEvent_t ev_fork = 0, ev_join = 0;
    if (!s2) {
        cudaStreamCreateWithFlags(&s2, cudaStreamNonBlocking);
        cudaEventCreateWithFlags(&ev_fork, cudaEventDisableTiming);
        cudaEventCreateWithFlags(&ev_join, cudaEventDisableTiming);
    }

    // fork: gemm1(+prep) on s2, CSR build (+ output seed) on the launch stream
    cudaEventRecord(ev_fork, 0);
    cudaStreamWaitEvent(s2, ev_fork, 0);
    k_gemm1<<<GEMM_BLOCKS + 1, 256, 0, s2>>>(x, W1, att_src1, att_dst1,
                                             W2, att_src2, att_dst2, Wg, bias2);
    cudaEventRecord(ev_join, s2);

    k_scatter<<<SCAT_BLOCKS + 1, 256>>>(ei, out, bg);

    cudaStreamWaitEvent(0, ev_join, 0);
    k_edge1<<<(N_NODES * 8 + 255) / 256, 256>>>(bias1);
    k_edge2<<<(N_NODES * 8 + 255) / 256, 256>>>(batch, out);
}